// round 13
// baseline (speedup 1.0000x reference)
#include <cuda_runtime.h>
#include <cuda_bf16.h>
#include <cuda_fp16.h>
#include <cstdint>

// Problem constants
#define B_    32
#define CIN_  64
#define Hh    32
#define Ww    32
#define CO_   64
#define KK    7
#define G_    8
#define PAD_  3
#define HP    38            // padded side
#define NPIX  (HP*HP)       // 1444

// Scratch (no cudaMalloc allowed)
__device__ float  g_q[B_ * Hh * Ww * CO_];       // [b][hw][o]  fp32
__device__ float  g_k[B_ * NPIX * CO_];          // [b][pp][o]  fp32
__device__ __half g_vh[B_ * NPIX * CO_];         // [b][pp][o]  fp16
// bf16 split weights, packed pairs: [n=m*64+oc][c2] (u32 = 2 bf16 along c)
__device__ uint32_t g_wh[3 * CO_ * 32];
__device__ uint32_t g_wl[3 * CO_ * 32];

// ---- packed fp32 helpers ---------------------------------------------------
#define PACKF(out, lo, hi) \
    asm("mov.b64 %0, {%1, %2};" : "=l"(out) : "f"(lo), "f"(hi))
#define UNPACKF(lo, hi, in) \
    asm("mov.b64 {%0, %1}, %2;" : "=f"(lo), "=f"(hi) : "l"(in))
#define FFMA2(d, a, b) \
    asm("fma.rn.f32x2 %0, %1, %2, %0;" : "+l"(d) : "l"(a), "l"(b))

// ---- bf16 HMMA m16n8k16 ----------------------------------------------------
__device__ __forceinline__ void mma16816(float* d, const uint32_t* a,
                                         uint32_t b0, uint32_t b1) {
    asm volatile(
        "mma.sync.aligned.m16n8k16.row.col.f32.bf16.bf16.f32 "
        "{%0,%1,%2,%3}, {%4,%5,%6,%7}, {%8,%9}, {%0,%1,%2,%3};"
        : "+f"(d[0]), "+f"(d[1]), "+f"(d[2]), "+f"(d[3])
        : "r"(a[0]), "r"(a[1]), "r"(a[2]), "r"(a[3]), "r"(b0), "r"(b1));
}

__device__ __forceinline__ uint32_t pack_bf16_hi(float x0, float x1,
                                                 float& r0, float& r1) {
    __nv_bfloat16 h0 = __float2bfloat16(x0);
    __nv_bfloat16 h1 = __float2bfloat16(x1);
    r0 = x0 - __bfloat162float(h0);
    r1 = x1 - __bfloat162float(h1);
    return ((uint32_t)__bfloat16_as_ushort(h1) << 16) | __bfloat16_as_ushort(h0);
}
__device__ __forceinline__ uint32_t pack_bf16(float x0, float x1) {
    return ((uint32_t)__bfloat16_as_ushort(__float2bfloat16(x1)) << 16) |
           __bfloat16_as_ushort(__float2bfloat16(x0));
}

// ---------------------------------------------------------------------------
// Util: weight split only (border handling moved into attn fill).
// ---------------------------------------------------------------------------
__global__ __launch_bounds__(512) void util_kernel(
    const float* __restrict__ wq,
    const float* __restrict__ wk,
    const float* __restrict__ wv) {
    int idx = blockIdx.x * 512 + threadIdx.x;    // 0..6143: n*32+c2
    int n = idx >> 5, c2 = idx & 31;
    int m = n >> 6, oc = n & 63;
    const float* W = (m == 0) ? wq : (m == 1 ? wk : wv);
    float v0 = W[oc * 64 + 2 * c2];
    float v1 = W[oc * 64 + 2 * c2 + 1];
    float r0, r1;
    g_wh[idx] = pack_bf16_hi(v0, v1, r0, r1);
    g_wl[idx] = pack_bf16(r0, r1);
}

// ---------------------------------------------------------------------------
// HMMA projection: CTA = 128 interior pixels of one batch, 256 threads.
// D[128,192] = Xsplit[128,64] x Wsplit[64,192], 3 bf16 products, fp32 acc.
// ---------------------------------------------------------------------------
#define SA      36                        // A row stride in u32
#define A_PLANE (128 * SA)                // 4608 u32
#define BROW    32                        // B row stride in u32
#define B_PLANE (192 * BROW)              // 6144 u32
#define OFF_AH  0
#define OFF_AL  (A_PLANE)
#define OFF_BH  (2 * A_PLANE)
#define OFF_BL  (2 * A_PLANE + B_PLANE)
#define SMEM_TC ((2 * A_PLANE + 2 * B_PLANE) * 4)   // 86016 bytes

__global__ __launch_bounds__(256) void proj_tc_kernel(const float* __restrict__ x) {
    extern __shared__ uint32_t sm32[];
    const int tid = threadIdx.x;
    const int b   = blockIdx.x >> 3;
    const int p0  = (blockIdx.x & 7) * 128;          // interior pixel base

    const float* xb = x + (size_t)b * 65536;
    for (int i = tid; i < 4096; i += 256) {
        int px = i & 127, c2 = i >> 7;
        float x0 = xb[(2 * c2) * 1024 + p0 + px];
        float x1 = xb[(2 * c2 + 1) * 1024 + p0 + px];
        float r0, r1;
        sm32[OFF_AH + px * SA + c2] = pack_bf16_hi(x0, x1, r0, r1);
        sm32[OFF_AL + px * SA + c2] = pack_bf16(r0, r1);
    }
    for (int i = tid; i < 6144; i += 256) {
        int n = i >> 5, c2 = i & 31;
        int sc = (c2 + 4 * (n & 7)) & 31;
        sm32[OFF_BH + n * BROW + sc] = g_wh[i];
        sm32[OFF_BL + n * BROW + sc] = g_wl[i];
    }
    __syncthreads();

    const int w   = tid >> 5;
    const int t   = tid & 31;
    const int qid = t >> 2;
    const int q4  = t & 3;

    uint32_t ah[4][4], al[4][4];
    {
        int r0 = 16 * w + qid;
#pragma unroll
        for (int kt = 0; kt < 4; kt++) {
            int cidx = kt * 8 + q4;
            ah[kt][0] = sm32[OFF_AH + r0 * SA + cidx];
            ah[kt][1] = sm32[OFF_AH + (r0 + 8) * SA + cidx];
            ah[kt][2] = sm32[OFF_AH + r0 * SA + cidx + 4];
            ah[kt][3] = sm32[OFF_AH + (r0 + 8) * SA + cidx + 4];
            al[kt][0] = sm32[OFF_AL + r0 * SA + cidx];
            al[kt][1] = sm32[OFF_AL + (r0 + 8) * SA + cidx];
            al[kt][2] = sm32[OFF_AL + r0 * SA + cidx + 4];
            al[kt][3] = sm32[OFF_AL + (r0 + 8) * SA + cidx + 4];
        }
    }

    const int pixA = p0 + 16 * w + qid;
    const int pixB = pixA + 8;
    const int ppA  = ((pixA >> 5) + PAD_) * HP + (pixA & 31) + PAD_;
    const int ppB  = ((pixB >> 5) + PAD_) * HP + (pixB & 31) + PAD_;
    const int rot  = 4 * qid;

#pragma unroll
    for (int m = 0; m < 3; m++) {
        float d[8][4];
#pragma unroll
        for (int nt = 0; nt < 8; nt++)
#pragma unroll
            for (int j = 0; j < 4; j++) d[nt][j] = 0.f;

#pragma unroll
        for (int kt = 0; kt < 4; kt++) {
            int c0 = kt * 8 + q4;
            int s0 = (c0 + rot) & 31;
            int s1 = (c0 + 4 + rot) & 31;
#pragma unroll
            for (int nt = 0; nt < 8; nt++) {
                int nb = (m * 64 + nt * 8 + qid) * BROW;
                uint32_t bh0 = sm32[OFF_BH + nb + s0];
                uint32_t bh1 = sm32[OFF_BH + nb + s1];
                uint32_t bl0 = sm32[OFF_BL + nb + s0];
                uint32_t bl1 = sm32[OFF_BL + nb + s1];
                mma16816(d[nt], ah[kt], bh0, bh1);
                mma16816(d[nt], ah[kt], bl0, bl1);
                mma16816(d[nt], al[kt], bh0, bh1);
            }
        }

        if (m == 0) {
            float* baseA = g_q + (size_t)(b * 1024 + pixA) * 64;
            float* baseB = g_q + (size_t)(b * 1024 + pixB) * 64;
#pragma unroll
            for (int nt = 0; nt < 8; nt++) {
                int c = nt * 8 + q4 * 2;
                *(float2*)(baseA + c) = make_float2(d[nt][0], d[nt][1]);
                *(float2*)(baseB + c) = make_float2(d[nt][2], d[nt][3]);
            }
        } else if (m == 1) {
            float* baseA = g_k + (size_t)(b * NPIX + ppA) * 64;
            float* baseB = g_k + (size_t)(b * NPIX + ppB) * 64;
#pragma unroll
            for (int nt = 0; nt < 8; nt++) {
                int c = nt * 8 + q4 * 2;
                *(float2*)(baseA + c) = make_float2(d[nt][0], d[nt][1]);
                *(float2*)(baseB + c) = make_float2(d[nt][2], d[nt][3]);
            }
        } else {
            __half* baseA = g_vh + (size_t)(b * NPIX + ppA) * 64;
            __half* baseB = g_vh + (size_t)(b * NPIX + ppB) * 64;
#pragma unroll
            for (int nt = 0; nt < 8; nt++) {
                int c = nt * 8 + q4 * 2;
                *(__half2*)(baseA + c) = __float22half2_rn(make_float2(d[nt][0], d[nt][1]));
                *(__half2*)(baseB + c) = __float22half2_rn(make_float2(d[nt][2], d[nt][3]));
            }
        }
    }
}

// ---------------------------------------------------------------------------
// Attention: CTA = (b, g, 8-row tile). 256 threads, thread = one pixel.
// k fp32 in smem (scores exact), v fp16 in smem (half crossbar traffic).
// Border pixels substituted with zero at fill time (= pad-projection of 0).
// ---------------------------------------------------------------------------
#define TROWS 8
#define TPIX  532   // (TROWS + KK - 1) * HP

__global__ __launch_bounds__(256) void attn_kernel(const float* __restrict__ rel_h,
                                                   const float* __restrict__ rel_w,
                                                   const float* __restrict__ cur,
                                                   float* __restrict__ out) {
    const int h0 = blockIdx.x * TROWS;
    const int g  = blockIdx.y;
    const int b  = blockIdx.z;

    __shared__ __align__(16) float k_s[2 * TPIX * 4];   // [c4-plane][pix][4]
    __shared__ __align__(16) uint4 v_s[TPIX];           // fp16x8 per pixel
    float4* ks4 = (float4*)k_s;

    const float4* gk4 = (const float4*)g_k + (size_t)(b * NPIX + h0 * HP) * 16 + g * 2;
    const uint4*  gv4 = (const uint4*)g_vh + (size_t)(b * NPIX + h0 * HP) * 8 + g;
    const float4  zf4 = make_float4(0.f, 0.f, 0.f, 0.f);
    const uint4   zu4 = make_uint4(0, 0, 0, 0);

    for (int idx = threadIdx.x; idx < 2 * TPIX; idx += 256) {
        int pp = idx >> 1, c4 = idx & 1;
        int row = pp / HP;
        int col = pp - row * HP;
        int y   = h0 + row;
        bool in = (y >= PAD_) && (y < PAD_ + Hh) && (col >= PAD_) && (col < PAD_ + Ww);
        ks4[c4 * TPIX + pp] = in ? gk4[pp * 16 + c4] : zf4;
    }
    for (int pp = threadIdx.x; pp < TPIX; pp += 256) {
        int row = pp / HP;
        int col = pp - row * HP;
        int y   = h0 + row;
        bool in = (y >= PAD_) && (y < PAD_ + Hh) && (col >= PAD_) && (col < PAD_ + Ww);
        v_s[pp] = in ? gv4[pp * 8] : zu4;
    }
    __syncthreads();

    const int r = threadIdx.x >> 5;
    const int w = threadIdx.x & 31;
    const int h = h0 + r;

    const float4* qp = (const float4*)(g_q + (size_t)(b * 1024 + h * 32 + w) * 64 + g * 8);
    float4 qa = qp[0], qb = qp[1];
    float q[8] = {qa.x, qa.y, qa.z, qa.w, qb.x, qb.y, qb.z, qb.w};
    unsigned long long qpk[4];
#pragma unroll
    for (int c = 0; c < 4; c++) PACKF(qpk[c], q[2 * c], q[2 * c + 1]);

    float rel[7];
    {
        const float* rb = (g < 4) ? (rel_h + g * 56) : (rel_w + (g - 4) * 56);
#pragma unroll
        for (int t = 0; t < 7; t++) {
            float s = 0.f;
#pragma unroll
            for (int c = 0; c < 8; c++) s += q[c] * rb[c * 7 + t];
            rel[t] = s;
        }
    }

    const ulonglong2* ks2 = (const ulonglong2*)k_s;

    float sc[49];
#pragma unroll
    for (int i = 0; i < 7; i++) {
        int base = (r + i) * HP + w;
#pragma unroll
        for (int j = 0; j < 7; j++) {
            int pix = base + j;
            ulonglong2 ka = ks2[pix];
            ulonglong2 kb = ks2[TPIX + pix];
            unsigned long long t;
            PACKF(t, (g < 4) ? rel[i] : rel[j], 0.f);
            FFMA2(t, ka.x, qpk[0]); FFMA2(t, ka.y, qpk[1]);
            FFMA2(t, kb.x, qpk[2]); FFMA2(t, kb.y, qpk[3]);
            float lo, hi; UNPACKF(lo, hi, t);
            sc[i * 7 + j] = lo + hi;
        }
    }

    float m = sc[0];
#pragma unroll
    for (int s = 1; s < 49; s++) m = fmaxf(m, sc[s]);
    float sum = 0.f;
#pragma unroll
    for (int s = 0; s < 49; s++) { sc[s] = __expf(sc[s] - m); sum += sc[s]; }

    float oa[8];
#pragma unroll
    for (int c = 0; c < 8; c++) oa[c] = 0.f;
#pragma unroll
    for (int i = 0; i < 7; i++) {
        int base = (r + i) * HP + w;
#pragma unroll
        for (int j = 0; j < 7; j++) {
            int pix = base + j;
            float p = sc[i * 7 + j];
            uint4 vv = v_s[pix];
            const __half2* hp = (const __half2*)&vv;
            float2 f0 = __half22float2(hp[0]);
            float2 f1 = __half22float2(hp[1]);
            float2 f2 = __half22float2(hp[2]);
            float2 f3 = __half22float2(hp[3]);
            oa[0] += p * f0.x; oa[1] += p * f0.y;
            oa[2] += p * f1.x; oa[3] += p * f1.y;
            oa[4] += p * f2.x; oa[5] += p * f2.y;
            oa[6] += p * f3.x; oa[7] += p * f3.y;
        }
    }

    float inv = 1.f / sum;
    int rr = min(h, 31 - h);
    int lo = (h <= 31 - h) ? rr : rr + 1;
    int hi = 31 - rr;
    float om = ((float)(rr - 15) + cur[g] * 16.f) / 3.f + 1.f;
    om = fminf(fmaxf(om, 0.f), 1.f);
    float mk = (w >= lo && w <= hi) ? om : 1.f;
    float scal = inv * mk;

    float* op = out + (size_t)(b * 64 + g * 8) * 1024 + h * 32 + w;
#pragma unroll
    for (int c = 0; c < 8; c++) op[c * 1024] = oa[c] * scal;
}

// ---------------------------------------------------------------------------
extern "C" void kernel_launch(void* const* d_in, const int* in_sizes, int n_in,
                              void* d_out, int out_size) {
    const float* x  = (const float*)d_in[0];
    const float* wq = (const float*)d_in[1];
    const float* wk = (const float*)d_in[2];
    const float* wv = (const float*)d_in[3];
    const float* rh = (const float*)d_in[4];
    const float* rw = (const float*)d_in[5];
    const float* cv = (const float*)d_in[6];
    float* out = (float*)d_out;

    cudaFuncSetAttribute(proj_tc_kernel,
                         cudaFuncAttributeMaxDynamicSharedMemorySize, SMEM_TC);

    util_kernel<<<12, 512>>>(wq, wk, wv);
    proj_tc_kernel<<<256, 256, SMEM_TC>>>(x);
    attn_kernel<<<dim3(Hh / TROWS, G_, B_), 256>>>(rh, rw, cv, out);
}